// round 4
// baseline (speedup 1.0000x reference)
#include <cuda_runtime.h>
#include <math.h>

// Problem constants (fixed by setup_inputs)
#define BB   4
#define CC   64
#define OO   64
#define HH   128
#define WW   128
#define HWSZ (HH * WW)

// Scratch for offset-conv output: [B][27][H][W]
__device__ float g_om[BB * 27 * HWSZ];

typedef unsigned long long u64;

// ---- packed fp32x2 helpers (Blackwell FFMA2 path) ----
__device__ __forceinline__ u64 dup2(float v) {
    u64 r; asm("mov.b64 %0, {%1, %1};" : "=l"(r) : "f"(v)); return r;
}
__device__ __forceinline__ void fma2(u64& d, u64 a, u64 b) {
    asm("fma.rn.f32x2 %0, %1, %2, %0;" : "+l"(d) : "l"(a), "l"(b));
}
__device__ __forceinline__ void unpack2(u64 v, float& lo, float& hi) {
    asm("mov.b64 {%0, %1}, %2;" : "=f"(lo), "=f"(hi) : "l"(v));
}

// ---------------------------------------------------------------------------
// Kernel 1: 3x3 conv producing 27 offset/mask channels (padded to 32 in smem).
// One CTA per (b, 2 rows). 512 threads. Thread tile 4o x 4px, o-paired f32x2.
// ---------------------------------------------------------------------------
#define K1_W_FLOATS (576 * 32)
#define K1_F_FLOATS (CC * 4 * 136)
#define K1_SMEM_BYTES ((K1_W_FLOATS + K1_F_FLOATS) * 4)

__global__ __launch_bounds__(512, 1)
void offset_conv_kernel(const float* __restrict__ feat,
                        const float* __restrict__ w_off,
                        const float* __restrict__ b_off)
{
    extern __shared__ float smem[];
    float* w_s    = smem;                 // [k=576][o=32]
    float* feat_s = smem + K1_W_FLOATS;   // [c][rr=4][136]

    const int y0  = blockIdx.x * 2;
    const int b   = blockIdx.y;
    const int tid = threadIdx.x;

    for (int idx = tid; idx < K1_W_FLOATS; idx += 512) {
        int o = idx & 31;
        int k = idx >> 5;
        int c = k / 9;
        int r = k - c * 9;
        w_s[idx] = (o < 27) ? w_off[(o * CC + c) * 9 + r] : 0.f;
    }
    const float* fb = feat + (size_t)b * CC * HWSZ;
    for (int idx = tid; idx < K1_F_FLOATS; idx += 512) {
        int xx = idx % 136;      // 0 maps to x=-1
        int t  = idx / 136;
        int rr = t & 3;
        int c  = t >> 2;
        int yy = y0 - 1 + rr;
        int xg = xx - 1;
        float v = 0.f;
        if (xx < 132 && yy >= 0 && yy < HH && xg >= 0 && xg < WW)
            v = fb[(c * HH + yy) * WW + xg];
        feat_s[idx] = v;
    }
    __syncthreads();

    const int o0   = (tid >> 6) * 4;        // warp-uniform
    const int px0  = (tid & 63) * 4;
    const int rowo = px0 >> 7;
    const int xloc = px0 & 127;

    u64 acc2[2][4];
#pragma unroll
    for (int j = 0; j < 2; j++)
#pragma unroll
        for (int i = 0; i < 4; i++) acc2[j][i] = 0ULL;

    for (int c = 0; c < CC; c++) {
#pragma unroll
        for (int ky = 0; ky < 3; ky++) {
            const float* row = &feat_s[(c * 4 + rowo + ky) * 136 + xloc];
            float4 fa = *(const float4*)row;
            float2 fb2 = *(const float2*)(row + 4);
            float f[6] = {fa.x, fa.y, fa.z, fa.w, fb2.x, fb2.y};
            u64 fd[6];
#pragma unroll
            for (int t = 0; t < 6; t++) fd[t] = dup2(f[t]);
#pragma unroll
            for (int kx = 0; kx < 3; kx++) {
                const ulonglong2 wp =
                    *(const ulonglong2*)&w_s[((c * 9 + ky * 3 + kx) << 5) + o0];
#pragma unroll
                for (int i = 0; i < 4; i++) {
                    fma2(acc2[0][i], wp.x, fd[i + kx]);
                    fma2(acc2[1][i], wp.y, fd[i + kx]);
                }
            }
        }
    }

    const int yout = y0 + rowo;
#pragma unroll
    for (int jp = 0; jp < 2; jp++) {
        float vlo[4], vhi[4];
#pragma unroll
        for (int i = 0; i < 4; i++) unpack2(acc2[jp][i], vlo[i], vhi[i]);
        int oA = o0 + 2 * jp;
        int oB = oA + 1;
        if (oA < 27) {
            float bo = b_off[oA];
            float* op = &g_om[((b * 27 + oA) * HH + yout) * WW + xloc];
            *(float4*)op = make_float4(vlo[0] + bo, vlo[1] + bo, vlo[2] + bo, vlo[3] + bo);
        }
        if (oB < 27) {
            float bo = b_off[oB];
            float* op = &g_om[((b * 27 + oB) * HH + yout) * WW + xloc];
            *(float4*)op = make_float4(vhi[0] + bo, vhi[1] + bo, vhi[2] + bo, vhi[3] + bo);
        }
    }
}

// ---------------------------------------------------------------------------
// Kernel 2: fused bilinear sampling + deform GEMM + bias + ReLU.
// One CTA per (b, 2 rows): 64 o x 256 px, K = 576. 512 threads.
// 3-stage software pipeline at 16-channel phase granularity (36 phases):
//   combine+STS(p) -> barrier -> issue raw gather LDGs(p+1) -> GEMM(p)
// so gather latency is covered by GEMM compute.
// smem: w_s[576][64] (144KB) + 2 x vals[16][256] (32KB).
// ---------------------------------------------------------------------------
#define K2_W      (576 * 64)
#define K2_CH     16
#define K2_VBUF   (K2_CH * 256)
#define K2_NPH    36
#define K2_SMEM_BYTES ((K2_W + 2 * K2_VBUF) * 4)

__global__ __launch_bounds__(512, 1)
void deform_gemm_kernel(const float* __restrict__ x,
                        const float* __restrict__ w_def,
                        const float* __restrict__ b_def,
                        float* __restrict__ out)
{
    extern __shared__ float smem[];
    float* w_s   = smem;                 // [k=576][o=64]
    float* vbuf0 = smem + K2_W;
    float* vbuf1 = smem + K2_W + K2_VBUF;

    const int y0  = blockIdx.x * 2;
    const int b   = blockIdx.y;
    const int tid = threadIdx.x;

    // load w_def: w_s[k*64 + o], k = c*9 + r
    for (int idx = tid; idx < K2_W; idx += 512) {
        int o = idx & 63;
        int k = idx >> 6;
        int c = k / 9;
        int r = k - c * 9;
        w_s[idx] = w_def[(o * CC + c) * 9 + r];
    }

    // GEMM identity: 8 o (4 pairs) x 4 px
    const int pxa = (tid & 63) * 4;
    const int o0  = (tid >> 6) * 8;     // warp-uniform
    // fill identity: one px, 8 channels
    const int fpx  = tid & 255;
    const int cb   = (tid >> 8) * 8;    // 0 or 8
    const int yrow = y0 + (fpx >> 7);
    const int gx   = fpx & 127;

    const float* xb  = x + (size_t)b * CC * HWSZ;
    const float* xcb = xb + cb * HWSZ;
    const int om_base = (b * 27 * HH + yrow) * WW + gx;

    u64 acc2[4][4];
#pragma unroll
    for (int j = 0; j < 4; j++)
#pragma unroll
        for (int i = 0; i < 4; i++) acc2[j][i] = 0ULL;

    float* bufs[2] = {vbuf0, vbuf1};

    float cw[4];
    int   ci[4];
    float L[32];

    // ---- params for a tap (corner weights + clamped indices) ----
    auto compute_params = [&](int tap) {
        float offx = g_om[om_base + tap * HWSZ];
        float offy = g_om[om_base + (9 + tap) * HWSZ];
        float mz   = g_om[om_base + (18 + tap) * HWSZ];
        float m    = 1.f / (1.f + __expf(-mz));
        float ys = (float)(yrow + tap / 3 - 1) + offy;
        float xs = (float)(gx + tap % 3 - 1) + offx;
        float y0f = floorf(ys), x0f = floorf(xs);
        float wy1 = ys - y0f,   wx1 = xs - x0f;
        int iy0 = (int)y0f, ix0 = (int)x0f;
#pragma unroll
        for (int corner = 0; corner < 4; corner++) {
            int oy = corner >> 1, ox = corner & 1;
            int yy = iy0 + oy, xx = ix0 + ox;
            bool valid = (yy >= 0) && (yy < HH) && (xx >= 0) && (xx < WW);
            float wy = oy ? wy1 : (1.f - wy1);
            float wx = ox ? wx1 : (1.f - wx1);
            cw[corner] = valid ? (wy * wx * m) : 0.f;
            ci[corner] = min(max(yy, 0), HH - 1) * WW + min(max(xx, 0), WW - 1);
        }
    };

    // ---- raw gather loads for a phase (channels cbase..cbase+15, ours: +cb..+cb+7)
    auto issue_loads = [&](int cbase) {
        const float* p0 = xcb + (size_t)cbase * HWSZ;
#pragma unroll
        for (int r = 0; r < 8; r++) {
            const float* xc = p0 + r * HWSZ;
            L[r * 4 + 0] = __ldg(xc + ci[0]);
            L[r * 4 + 1] = __ldg(xc + ci[1]);
            L[r * 4 + 2] = __ldg(xc + ci[2]);
            L[r * 4 + 3] = __ldg(xc + ci[3]);
        }
    };

    // prologue: params for tap 0, loads for phase 0
    compute_params(0);
    issue_loads(0);

    for (int p = 0; p < K2_NPH; p++) {
        const int tap = p >> 2;
        const int cc  = (p & 3) * K2_CH;
        float* vb = bufs[p & 1];

        // 1) combine + STS for phase p (consumes L)
        {
            float* bp = vb + fpx;
#pragma unroll
            for (int r = 0; r < 8; r++) {
                float v = cw[0] * L[r * 4 + 0] + cw[1] * L[r * 4 + 1]
                        + cw[2] * L[r * 4 + 2] + cw[3] * L[r * 4 + 3];
                bp[(cb + r) * 256] = v;
            }
        }
        __syncthreads();

        // 2) issue gather loads for phase p+1 (latency covered by GEMM below)
        if (p < K2_NPH - 1) {
            int pn = p + 1;
            if ((pn & 3) == 0) compute_params(pn >> 2);
            issue_loads((pn & 3) * K2_CH);
        }

        // 3) GEMM over phase p's 16-channel chunk
#pragma unroll 8
        for (int cl = 0; cl < K2_CH; cl++) {
            const int k = (cc + cl) * 9 + tap;
            const float* wp = &w_s[k * 64 + o0];
            const ulonglong2 w01 = *(const ulonglong2*)wp;
            const ulonglong2 w23 = *(const ulonglong2*)(wp + 4);
            const float4 v = *(const float4*)&vb[cl * 256 + pxa];
            u64 vd[4] = {dup2(v.x), dup2(v.y), dup2(v.z), dup2(v.w)};
            u64 wv[4] = {w01.x, w01.y, w23.x, w23.y};
#pragma unroll
            for (int j = 0; j < 4; j++)
#pragma unroll
                for (int i = 0; i < 4; i++)
                    fma2(acc2[j][i], wv[j], vd[i]);
        }
        __syncthreads();
    }

    // epilogue: unpack o-pairs, bias + relu, float4 stores
    const int yr2  = y0 + (pxa >> 7);
    const int xcol = pxa & 127;
#pragma unroll
    for (int jp = 0; jp < 4; jp++) {
        float vlo[4], vhi[4];
#pragma unroll
        for (int i = 0; i < 4; i++) unpack2(acc2[jp][i], vlo[i], vhi[i]);
        int oA = o0 + 2 * jp;
        int oB = oA + 1;
        float bA = b_def[oA], bB = b_def[oB];
        float* opA = out + ((size_t)(b * OO + oA) * HH + yr2) * WW + xcol;
        float* opB = out + ((size_t)(b * OO + oB) * HH + yr2) * WW + xcol;
        *(float4*)opA = make_float4(fmaxf(vlo[0] + bA, 0.f), fmaxf(vlo[1] + bA, 0.f),
                                    fmaxf(vlo[2] + bA, 0.f), fmaxf(vlo[3] + bA, 0.f));
        *(float4*)opB = make_float4(fmaxf(vhi[0] + bB, 0.f), fmaxf(vhi[1] + bB, 0.f),
                                    fmaxf(vhi[2] + bB, 0.f), fmaxf(vhi[3] + bB, 0.f));
    }
}

// ---------------------------------------------------------------------------
extern "C" void kernel_launch(void* const* d_in, const int* in_sizes, int n_in,
                              void* d_out, int out_size)
{
    const float* x     = (const float*)d_in[0];
    const float* feat  = (const float*)d_in[1];
    const float* w_off = (const float*)d_in[2];
    const float* b_off = (const float*)d_in[3];
    const float* w_def = (const float*)d_in[4];
    const float* b_def = (const float*)d_in[5];
    float* out = (float*)d_out;

    cudaFuncSetAttribute(offset_conv_kernel,
                         cudaFuncAttributeMaxDynamicSharedMemorySize, K1_SMEM_BYTES);
    cudaFuncSetAttribute(deform_gemm_kernel,
                         cudaFuncAttributeMaxDynamicSharedMemorySize, K2_SMEM_BYTES);

    dim3 grid(HH / 2, BB);
    offset_conv_kernel<<<grid, 512, K1_SMEM_BYTES>>>(feat, w_off, b_off);
    deform_gemm_kernel<<<grid, 512, K2_SMEM_BYTES>>>(x, w_def, b_def, out);
}

// round 7
// speedup vs baseline: 1.4972x; 1.4972x over previous
#include <cuda_runtime.h>
#include <cuda_bf16.h>
#include <math.h>
#include <stdint.h>

// Problem constants (fixed by setup_inputs)
#define BB   4
#define CC   64
#define OO   64
#define HH   128
#define WW   128
#define HWSZ (HH * WW)

// Scratch: offset-conv output [B][27][H][W]; split weights [hi|lo][o][584]
#define WPITCH 584
__device__ float g_om[BB * 27 * HWSZ];
__device__ unsigned short g_w2[2 * OO * WPITCH];

typedef unsigned long long u64;

// ---- packed fp32x2 helpers (Blackwell FFMA2, used by K1) ----
__device__ __forceinline__ u64 dup2(float v) {
    u64 r; asm("mov.b64 %0, {%1, %1};" : "=l"(r) : "f"(v)); return r;
}
__device__ __forceinline__ void fma2(u64& d, u64 a, u64 b) {
    asm("fma.rn.f32x2 %0, %1, %2, %0;" : "+l"(d) : "l"(a), "l"(b));
}
__device__ __forceinline__ void unpack2(u64 v, float& lo, float& hi) {
    asm("mov.b64 {%0, %1}, %2;" : "=f"(lo), "=f"(hi) : "l"(v));
}

__device__ __forceinline__ uint32_t smem_u32(const void* p) {
    uint32_t a;
    asm("{ .reg .u64 t; cvta.to.shared.u64 t, %1; cvt.u32.u64 %0, t; }"
        : "=r"(a) : "l"(p));
    return a;
}
__device__ __forceinline__ void ldsm4(uint32_t* r, uint32_t addr) {
    asm volatile("ldmatrix.sync.aligned.m8n8.x4.shared.b16 {%0,%1,%2,%3}, [%4];"
        : "=r"(r[0]), "=r"(r[1]), "=r"(r[2]), "=r"(r[3]) : "r"(addr));
}
__device__ __forceinline__ void mma_bf16(float* d, const uint32_t* a, const uint32_t* b) {
    asm volatile(
        "mma.sync.aligned.m16n8k16.row.col.f32.bf16.bf16.f32 "
        "{%0,%1,%2,%3}, {%4,%5,%6,%7}, {%8,%9}, {%0,%1,%2,%3};"
        : "+f"(d[0]), "+f"(d[1]), "+f"(d[2]), "+f"(d[3])
        : "r"(a[0]), "r"(a[1]), "r"(a[2]), "r"(a[3]), "r"(b[0]), "r"(b[1]));
}

// ---------------------------------------------------------------------------
// Prep: split w_def into bf16 hi/lo, layout [o][k=tap*64+c], pitch 584.
// ---------------------------------------------------------------------------
__global__ void prep_w_kernel(const float* __restrict__ w_def)
{
    int o = blockIdx.x;
    for (int col = threadIdx.x; col < WPITCH; col += blockDim.x) {
        unsigned short h = 0, l = 0;
        if (col < 576) {
            int tap = col >> 6, c = col & 63;
            float w = w_def[(o * CC + c) * 9 + tap];
            __nv_bfloat16 hb = __float2bfloat16(w);
            __nv_bfloat16 lb = __float2bfloat16(w - __bfloat162float(hb));
            h = __bfloat16_as_ushort(hb);
            l = __bfloat16_as_ushort(lb);
        }
        g_w2[o * WPITCH + col] = h;
        g_w2[OO * WPITCH + o * WPITCH + col] = l;
    }
}

// ---------------------------------------------------------------------------
// Kernel 1: 3x3 conv producing 27 offset/mask channels (FFMA2, unchanged).
// ---------------------------------------------------------------------------
#define K1_W_FLOATS (576 * 32)
#define K1_F_FLOATS (CC * 4 * 136)
#define K1_SMEM_BYTES ((K1_W_FLOATS + K1_F_FLOATS) * 4)

__global__ __launch_bounds__(512, 1)
void offset_conv_kernel(const float* __restrict__ feat,
                        const float* __restrict__ w_off,
                        const float* __restrict__ b_off)
{
    extern __shared__ float smem[];
    float* w_s    = smem;
    float* feat_s = smem + K1_W_FLOATS;

    const int y0  = blockIdx.x * 2;
    const int b   = blockIdx.y;
    const int tid = threadIdx.x;

    for (int idx = tid; idx < K1_W_FLOATS; idx += 512) {
        int o = idx & 31;
        int k = idx >> 5;
        int c = k / 9;
        int r = k - c * 9;
        w_s[idx] = (o < 27) ? w_off[(o * CC + c) * 9 + r] : 0.f;
    }
    const float* fb = feat + (size_t)b * CC * HWSZ;
    for (int idx = tid; idx < K1_F_FLOATS; idx += 512) {
        int xx = idx % 136;
        int t  = idx / 136;
        int rr = t & 3;
        int c  = t >> 2;
        int yy = y0 - 1 + rr;
        int xg = xx - 1;
        float v = 0.f;
        if (xx < 132 && yy >= 0 && yy < HH && xg >= 0 && xg < WW)
            v = fb[(c * HH + yy) * WW + xg];
        feat_s[idx] = v;
    }
    __syncthreads();

    const int o0   = (tid >> 6) * 4;
    const int px0  = (tid & 63) * 4;
    const int rowo = px0 >> 7;
    const int xloc = px0 & 127;

    u64 acc2[2][4];
#pragma unroll
    for (int j = 0; j < 2; j++)
#pragma unroll
        for (int i = 0; i < 4; i++) acc2[j][i] = 0ULL;

    for (int c = 0; c < CC; c++) {
#pragma unroll
        for (int ky = 0; ky < 3; ky++) {
            const float* row = &feat_s[(c * 4 + rowo + ky) * 136 + xloc];
            float4 fa = *(const float4*)row;
            float2 fb2 = *(const float2*)(row + 4);
            float f[6] = {fa.x, fa.y, fa.z, fa.w, fb2.x, fb2.y};
            u64 fd[6];
#pragma unroll
            for (int t = 0; t < 6; t++) fd[t] = dup2(f[t]);
#pragma unroll
            for (int kx = 0; kx < 3; kx++) {
                const ulonglong2 wp =
                    *(const ulonglong2*)&w_s[((c * 9 + ky * 3 + kx) << 5) + o0];
#pragma unroll
                for (int i = 0; i < 4; i++) {
                    fma2(acc2[0][i], wp.x, fd[i + kx]);
                    fma2(acc2[1][i], wp.y, fd[i + kx]);
                }
            }
        }
    }

    const int yout = y0 + rowo;
#pragma unroll
    for (int jp = 0; jp < 2; jp++) {
        float vlo[4], vhi[4];
#pragma unroll
        for (int i = 0; i < 4; i++) unpack2(acc2[jp][i], vlo[i], vhi[i]);
        int oA = o0 + 2 * jp;
        int oB = oA + 1;
        if (oA < 27) {
            float bo = b_off[oA];
            float* op = &g_om[((b * 27 + oA) * HH + yout) * WW + xloc];
            *(float4*)op = make_float4(vlo[0] + bo, vlo[1] + bo, vlo[2] + bo, vlo[3] + bo);
        }
        if (oB < 27) {
            float bo = b_off[oB];
            float* op = &g_om[((b * 27 + oB) * HH + yout) * WW + xloc];
            *(float4*)op = make_float4(vhi[0] + bo, vhi[1] + bo, vhi[2] + bo, vhi[3] + bo);
        }
    }
}

// ---------------------------------------------------------------------------
// Kernel 2: deform-GEMM on tensor cores via mma.sync bf16 hi/lo split.
// One CTA per (b, 2 rows): D[256 px][64 o], K=576 (k = tap*64 + c).
// 512 threads / 16 warps; warp w owns px block 16w x all 64 o (8 frags).
// Phase (18 total = 9 taps x 2 chunks of 32 ch):
//   gather-fill A[256][32] bf16 hi+lo -> sync -> 48 mma/warp -> sync.
// smem: Whi[64][584] + Wlo (146KB) + Ahi[256][40] + Alo (40KB) = 186KB.
// ---------------------------------------------------------------------------
#define SM_WHI 0
#define SM_WLO (OO * WPITCH * 2)                 // 74752
#define SM_AHI (2 * OO * WPITCH * 2)             // 149504
#define SM_ALO (SM_AHI + 256 * 80)               // 169984
#define K2_SMEM (SM_ALO + 256 * 80)              // 190464

__global__ __launch_bounds__(512, 1)
void deform_mma_kernel(const float* __restrict__ x,
                       const float* __restrict__ b_def,
                       float* __restrict__ out)
{
    extern __shared__ char smc[];
    const uint32_t sb = smem_u32(smc);

    const int y0  = blockIdx.x * 2;
    const int b   = blockIdx.y;
    const int tid = threadIdx.x;
    const int warp = tid >> 5;
    const int lane = tid & 31;

    // stage split weights (149504 B) into smem
    {
        const uint4* src = (const uint4*)g_w2;
        uint4* dst = (uint4*)smc;
        for (int i = tid; i < (2 * OO * WPITCH * 2) / 16; i += 512)
            dst[i] = src[i];
    }

    // fill identity: px = tid&255, channel group = (tid>>8)*16
    const int px    = tid & 255;
    const int chg   = (tid >> 8) * 16;
    const int yrow  = y0 + (px >> 7);
    const int gx    = px & 127;
    const float* xb = x + (size_t)b * CC * HWSZ;
    const int ombase = (b * 27 * HH + yrow) * WW + gx;

    // mma identity
    const int px0 = warp * 16;

    float acc[8][4];
#pragma unroll
    for (int ob = 0; ob < 8; ob++)
#pragma unroll
        for (int i = 0; i < 4; i++) acc[ob][i] = 0.f;

    // precomputed ldmatrix lane addressing
    const uint32_t a_row  = px0 + (lane & 15);
    const uint32_t a_colb = (lane >> 4) * 16;
    const uint32_t ahiA = sb + SM_AHI + a_row * 80 + a_colb;
    const uint32_t aloA = sb + SM_ALO + a_row * 80 + a_colb;
    const int bg  = lane >> 3;
    const int bl8 = lane & 7;
    const uint32_t b_row_off = ((bg >> 1) * 8 + bl8) * (WPITCH * 2);
    const uint32_t b_k8     = (bg & 1) * 16;     // byte offset for +8 k

    for (int tap = 0; tap < 9; tap++) {
        // sampling params once per (tap, px)
        float offx = g_om[ombase + tap * HWSZ];
        float offy = g_om[ombase + (9 + tap) * HWSZ];
        float mz   = g_om[ombase + (18 + tap) * HWSZ];
        float m    = 1.f / (1.f + __expf(-mz));
        float ys = (float)(yrow + tap / 3 - 1) + offy;
        float xs = (float)(gx + tap % 3 - 1) + offx;
        float y0f = floorf(ys), x0f = floorf(xs);
        float wy1 = ys - y0f,   wx1 = xs - x0f;
        int iy0 = (int)y0f, ix0 = (int)x0f;
        float cw[4];
        int   ci[4];
#pragma unroll
        for (int corner = 0; corner < 4; corner++) {
            int oy = corner >> 1, ox = corner & 1;
            int yy = iy0 + oy, xx = ix0 + ox;
            bool valid = (yy >= 0) && (yy < HH) && (xx >= 0) && (xx < WW);
            float wy = oy ? wy1 : (1.f - wy1);
            float wx = ox ? wx1 : (1.f - wx1);
            cw[corner] = valid ? (wy * wx * m) : 0.f;
            ci[corner] = min(max(yy, 0), HH - 1) * WW + min(max(xx, 0), WW - 1);
        }

        for (int half = 0; half < 2; half++) {
            // ---- fill A tile: 16 channels at this px ----
            {
                const int cbase = half * 32 + chg;     // global channel base
                char* ahp = smc + SM_AHI + px * 80 + chg * 2;
                char* alp = smc + SM_ALO + px * 80 + chg * 2;
#pragma unroll
                for (int j = 0; j < 4; j++) {
                    float v[4];
#pragma unroll
                    for (int q = 0; q < 4; q++) {
                        const float* xc = xb + (size_t)(cbase + 4 * j + q) * HWSZ;
                        v[q] = cw[0] * __ldg(xc + ci[0]) + cw[1] * __ldg(xc + ci[1])
                             + cw[2] * __ldg(xc + ci[2]) + cw[3] * __ldg(xc + ci[3]);
                    }
                    unsigned short h[4], l[4];
#pragma unroll
                    for (int q = 0; q < 4; q++) {
                        __nv_bfloat16 hb = __float2bfloat16(v[q]);
                        __nv_bfloat16 lb = __float2bfloat16(v[q] - __bfloat162float(hb));
                        h[q] = __bfloat16_as_ushort(hb);
                        l[q] = __bfloat16_as_ushort(lb);
                    }
                    uint2 hp, lp;
                    hp.x = ((uint32_t)h[1] << 16) | h[0];
                    hp.y = ((uint32_t)h[3] << 16) | h[2];
                    lp.x = ((uint32_t)l[1] << 16) | l[0];
                    lp.y = ((uint32_t)l[3] << 16) | l[2];
                    *(uint2*)(ahp + 8 * j) = hp;
                    *(uint2*)(alp + 8 * j) = lp;
                }
            }
            __syncthreads();

            // ---- mma over this 32-k chunk ----
#pragma unroll
            for (int ks = 0; ks < 2; ks++) {
                const int kglob = tap * 64 + half * 32 + ks * 16;
                uint32_t ah[4], al[4];
                ldsm4(ah, ahiA + ks * 32);
                ldsm4(al, aloA + ks * 32);
                uint32_t bh[16], bl[16];
                const uint32_t bcol = kglob * 2 + b_k8;
#pragma unroll
                for (int obp = 0; obp < 4; obp++) {
                    uint32_t roff = (uint32_t)(obp * 16) * (WPITCH * 2) + b_row_off + bcol;
                    ldsm4(&bh[obp * 4], sb + SM_WHI + roff);
                    ldsm4(&bl[obp * 4], sb + SM_WLO + roff);
                }
#pragma unroll
                for (int ob = 0; ob < 8; ob++) mma_bf16(acc[ob], ah, &bh[ob * 2]);
#pragma unroll
                for (int ob = 0; ob < 8; ob++) mma_bf16(acc[ob], ah, &bl[ob * 2]);
#pragma unroll
                for (int ob = 0; ob < 8; ob++) mma_bf16(acc[ob], al, &bh[ob * 2]);
            }
            __syncthreads();
        }
    }

    // ---- epilogue: bias + relu ----
    {
        const int prow = px0 + (lane >> 2);
        const int row1 = y0 + (prow >> 7);
        const int x1   = prow & 127;
        const int prow2 = prow + 8;
        const int row2 = y0 + (prow2 >> 7);
        const int x2   = prow2 & 127;
#pragma unroll
        for (int ob = 0; ob < 8; ob++) {
            int o = ob * 8 + (lane & 3) * 2;
            float b0v = __ldg(b_def + o);
            float b1v = __ldg(b_def + o + 1);
            float* p1 = out + (((size_t)(b * OO + o) * HH + row1) * WW + x1);
            float* p2 = out + (((size_t)(b * OO + o) * HH + row2) * WW + x2);
            p1[0]    = fmaxf(acc[ob][0] + b0v, 0.f);
            p1[HWSZ] = fmaxf(acc[ob][1] + b1v, 0.f);
            p2[0]    = fmaxf(acc[ob][2] + b0v, 0.f);
            p2[HWSZ] = fmaxf(acc[ob][3] + b1v, 0.f);
        }
    }
}

// ---------------------------------------------------------------------------
extern "C" void kernel_launch(void* const* d_in, const int* in_sizes, int n_in,
                              void* d_out, int out_size)
{
    const float* x     = (const float*)d_in[0];
    const float* feat  = (const float*)d_in[1];
    const float* w_off = (const float*)d_in[2];
    const float* b_off = (const float*)d_in[3];
    const float* w_def = (const float*)d_in[4];
    const float* b_def = (const float*)d_in[5];
    float* out = (float*)d_out;

    cudaFuncSetAttribute(offset_conv_kernel,
                         cudaFuncAttributeMaxDynamicSharedMemorySize, K1_SMEM_BYTES);
    cudaFuncSetAttribute(deform_mma_kernel,
                         cudaFuncAttributeMaxDynamicSharedMemorySize, K2_SMEM);

    prep_w_kernel<<<OO, 128>>>(w_def);
    dim3 grid1(HH / 2, BB);
    offset_conv_kernel<<<grid1, 512, K1_SMEM_BYTES>>>(feat, w_off, b_off);
    dim3 grid2(HH / 2, BB);
    deform_mma_kernel<<<grid2, 512, K2_SMEM>>>(x, b_def, out);
}

// round 8
// speedup vs baseline: 1.5072x; 1.0067x over previous
#include <cuda_runtime.h>
#include <cuda_bf16.h>
#include <math.h>
#include <stdint.h>

// Problem constants (fixed by setup_inputs)
#define BB   4
#define CC   64
#define OO   64
#define HH   128
#define WW   128
#define HWSZ (HH * WW)

// Scratch: offset-conv output [B][27][H][W]; split weights [hi|lo][o][584]
#define WPITCH 584
__device__ float g_om[BB * 27 * HWSZ];
__device__ unsigned short g_w2[2 * OO * WPITCH];

typedef unsigned long long u64;

// ---- packed fp32x2 helpers (Blackwell FFMA2, used by K1) ----
__device__ __forceinline__ u64 dup2(float v) {
    u64 r; asm("mov.b64 %0, {%1, %1};" : "=l"(r) : "f"(v)); return r;
}
__device__ __forceinline__ void fma2(u64& d, u64 a, u64 b) {
    asm("fma.rn.f32x2 %0, %1, %2, %0;" : "+l"(d) : "l"(a), "l"(b));
}
__device__ __forceinline__ void unpack2(u64 v, float& lo, float& hi) {
    asm("mov.b64 {%0, %1}, %2;" : "=f"(lo), "=f"(hi) : "l"(v));
}

__device__ __forceinline__ uint32_t smem_u32(const void* p) {
    uint32_t a;
    asm("{ .reg .u64 t; cvta.to.shared.u64 t, %1; cvt.u32.u64 %0, t; }"
        : "=r"(a) : "l"(p));
    return a;
}
__device__ __forceinline__ void ldsm4(uint32_t* r, uint32_t addr) {
    asm volatile("ldmatrix.sync.aligned.m8n8.x4.shared.b16 {%0,%1,%2,%3}, [%4];"
        : "=r"(r[0]), "=r"(r[1]), "=r"(r[2]), "=r"(r[3]) : "r"(addr));
}
__device__ __forceinline__ void mma_bf16(float* d, const uint32_t* a, const uint32_t* b) {
    asm volatile(
        "mma.sync.aligned.m16n8k16.row.col.f32.bf16.bf16.f32 "
        "{%0,%1,%2,%3}, {%4,%5,%6,%7}, {%8,%9}, {%0,%1,%2,%3};"
        : "+f"(d[0]), "+f"(d[1]), "+f"(d[2]), "+f"(d[3])
        : "r"(a[0]), "r"(a[1]), "r"(a[2]), "r"(a[3]), "r"(b[0]), "r"(b[1]));
}

// ---------------------------------------------------------------------------
// Prep: split w_def into bf16 hi/lo, layout [o][k=tap*64+c], pitch 584.
// ---------------------------------------------------------------------------
__global__ void prep_w_kernel(const float* __restrict__ w_def)
{
    int o = blockIdx.x;
    int col = blockIdx.y * 128 + threadIdx.x;
    if (col >= WPITCH) return;
    unsigned short h = 0, l = 0;
    if (col < 576) {
        int tap = col >> 6, c = col & 63;
        float w = w_def[(o * CC + c) * 9 + tap];
        __nv_bfloat16 hb = __float2bfloat16(w);
        __nv_bfloat16 lb = __float2bfloat16(w - __bfloat162float(hb));
        h = __bfloat16_as_ushort(hb);
        l = __bfloat16_as_ushort(lb);
    }
    g_w2[o * WPITCH + col] = h;
    g_w2[OO * WPITCH + o * WPITCH + col] = l;
}

// ---------------------------------------------------------------------------
// Kernel 1: 3x3 conv producing 27 offset/mask channels (FFMA2, unchanged).
// ---------------------------------------------------------------------------
#define K1_W_FLOATS (576 * 32)
#define K1_F_FLOATS (CC * 4 * 136)
#define K1_SMEM_BYTES ((K1_W_FLOATS + K1_F_FLOATS) * 4)

__global__ __launch_bounds__(512, 1)
void offset_conv_kernel(const float* __restrict__ feat,
                        const float* __restrict__ w_off,
                        const float* __restrict__ b_off)
{
    extern __shared__ float smem[];
    float* w_s    = smem;
    float* feat_s = smem + K1_W_FLOATS;

    const int y0  = blockIdx.x * 2;
    const int b   = blockIdx.y;
    const int tid = threadIdx.x;

    for (int idx = tid; idx < K1_W_FLOATS; idx += 512) {
        int o = idx & 31;
        int k = idx >> 5;
        int c = k / 9;
        int r = k - c * 9;
        w_s[idx] = (o < 27) ? w_off[(o * CC + c) * 9 + r] : 0.f;
    }
    const float* fb = feat + (size_t)b * CC * HWSZ;
    for (int idx = tid; idx < K1_F_FLOATS; idx += 512) {
        int xx = idx % 136;
        int t  = idx / 136;
        int rr = t & 3;
        int c  = t >> 2;
        int yy = y0 - 1 + rr;
        int xg = xx - 1;
        float v = 0.f;
        if (xx < 132 && yy >= 0 && yy < HH && xg >= 0 && xg < WW)
            v = fb[(c * HH + yy) * WW + xg];
        feat_s[idx] = v;
    }
    __syncthreads();

    const int o0   = (tid >> 6) * 4;
    const int px0  = (tid & 63) * 4;
    const int rowo = px0 >> 7;
    const int xloc = px0 & 127;

    u64 acc2[2][4];
#pragma unroll
    for (int j = 0; j < 2; j++)
#pragma unroll
        for (int i = 0; i < 4; i++) acc2[j][i] = 0ULL;

    for (int c = 0; c < CC; c++) {
#pragma unroll
        for (int ky = 0; ky < 3; ky++) {
            const float* row = &feat_s[(c * 4 + rowo + ky) * 136 + xloc];
            float4 fa = *(const float4*)row;
            float2 fb2 = *(const float2*)(row + 4);
            float f[6] = {fa.x, fa.y, fa.z, fa.w, fb2.x, fb2.y};
            u64 fd[6];
#pragma unroll
            for (int t = 0; t < 6; t++) fd[t] = dup2(f[t]);
#pragma unroll
            for (int kx = 0; kx < 3; kx++) {
                const ulonglong2 wp =
                    *(const ulonglong2*)&w_s[((c * 9 + ky * 3 + kx) << 5) + o0];
#pragma unroll
                for (int i = 0; i < 4; i++) {
                    fma2(acc2[0][i], wp.x, fd[i + kx]);
                    fma2(acc2[1][i], wp.y, fd[i + kx]);
                }
            }
        }
    }

    const int yout = y0 + rowo;
#pragma unroll
    for (int jp = 0; jp < 2; jp++) {
        float vlo[4], vhi[4];
#pragma unroll
        for (int i = 0; i < 4; i++) unpack2(acc2[jp][i], vlo[i], vhi[i]);
        int oA = o0 + 2 * jp;
        int oB = oA + 1;
        if (oA < 27) {
            float bo = b_off[oA];
            float* op = &g_om[((b * 27 + oA) * HH + yout) * WW + xloc];
            *(float4*)op = make_float4(vlo[0] + bo, vlo[1] + bo, vlo[2] + bo, vlo[3] + bo);
        }
        if (oB < 27) {
            float bo = b_off[oB];
            float* op = &g_om[((b * 27 + oB) * HH + yout) * WW + xloc];
            *(float4*)op = make_float4(vhi[0] + bo, vhi[1] + bo, vhi[2] + bo, vhi[3] + bo);
        }
    }
}

// ---------------------------------------------------------------------------
// Kernel 2: deform-GEMM on tensor cores, mma.sync bf16 hi/lo split,
// SOFTWARE-PIPELINED: double-buffered A tiles, one barrier per phase.
//   per phase p (18 = 9 taps x 2 halves):  fill(p+1) ; mma(p) ; barrier
// smem: Whi+Wlo (146KB) + 2 x (Ahi[256][40] + Alo) (80KB) = 231424 B.
// ---------------------------------------------------------------------------
#define SM_WHI 0
#define SM_WLO (OO * WPITCH * 2)                 // 74752
#define SM_A   (2 * OO * WPITCH * 2)             // 149504
#define A_HALF 20480                             // 256*80
#define A_BUF  (2 * A_HALF)                      // hi+lo per buffer
#define K2_SMEM (SM_A + 2 * A_BUF)               // 231424

__global__ __launch_bounds__(512, 1)
void deform_mma_kernel(const float* __restrict__ x,
                       const float* __restrict__ b_def,
                       float* __restrict__ out)
{
    extern __shared__ char smc[];
    const uint32_t sb = smem_u32(smc);

    const int y0  = blockIdx.x * 2;
    const int b   = blockIdx.y;
    const int tid = threadIdx.x;
    const int warp = tid >> 5;
    const int lane = tid & 31;

    // stage split weights (149504 B) into smem
    {
        const uint4* src = (const uint4*)g_w2;
        uint4* dst = (uint4*)smc;
        for (int i = tid; i < (2 * OO * WPITCH * 2) / 16; i += 512)
            dst[i] = src[i];
    }

    // fill identity: px = tid&255, channel group = (tid>>8)*16
    const int px    = tid & 255;
    const int chg   = (tid >> 8) * 16;
    const int yrow  = y0 + (px >> 7);
    const int gx    = px & 127;
    const float* xb = x + (size_t)b * CC * HWSZ;
    const int ombase = (b * 27 * HH + yrow) * WW + gx;

    // mma identity
    const int px0 = warp * 16;

    float acc[8][4];
#pragma unroll
    for (int ob = 0; ob < 8; ob++)
#pragma unroll
        for (int i = 0; i < 4; i++) acc[ob][i] = 0.f;

    // precomputed ldmatrix lane addressing
    const uint32_t a_row  = px0 + (lane & 15);
    const uint32_t a_colb = (lane >> 4) * 16;
    const uint32_t aA = sb + SM_A + a_row * 80 + a_colb;
    const int bg  = lane >> 3;
    const int bl8 = lane & 7;
    const uint32_t b_row_off = ((bg >> 1) * 8 + bl8) * (WPITCH * 2);
    const uint32_t b_k8     = (bg & 1) * 16;     // byte offset for +8 k

    // per-tap sampling params (live across phases)
    float cw[4];
    int   ci[4];

    auto compute_params = [&](int tap) {
        float offx = g_om[ombase + tap * HWSZ];
        float offy = g_om[ombase + (9 + tap) * HWSZ];
        float mz   = g_om[ombase + (18 + tap) * HWSZ];
        float m    = 1.f / (1.f + __expf(-mz));
        float ys = (float)(yrow + tap / 3 - 1) + offy;
        float xs = (float)(gx + tap % 3 - 1) + offx;
        float y0f = floorf(ys), x0f = floorf(xs);
        float wy1 = ys - y0f,   wx1 = xs - x0f;
        int iy0 = (int)y0f, ix0 = (int)x0f;
#pragma unroll
        for (int corner = 0; corner < 4; corner++) {
            int oy = corner >> 1, ox = corner & 1;
            int yy = iy0 + oy, xx = ix0 + ox;
            bool valid = (yy >= 0) && (yy < HH) && (xx >= 0) && (xx < WW);
            float wy = oy ? wy1 : (1.f - wy1);
            float wx = ox ? wx1 : (1.f - wx1);
            cw[corner] = valid ? (wy * wx * m) : 0.f;
            ci[corner] = min(max(yy, 0), HH - 1) * WW + min(max(xx, 0), WW - 1);
        }
    };

    // fill phase pn into buffer pn&1 (new tap params when entering even half)
    auto fill = [&](int pn) {
        const int tapn = pn >> 1;
        const int halfn = pn & 1;
        if (halfn == 0) compute_params(tapn);
        const int cbase = halfn * 32 + chg;
        char* ahp = smc + SM_A + halfn * A_BUF + px * 80 + chg * 2;
        char* alp = ahp + A_HALF;
#pragma unroll
        for (int j = 0; j < 4; j++) {
            float v[4];
#pragma unroll
            for (int q = 0; q < 4; q++) {
                const float* xc = xb + (size_t)(cbase + 4 * j + q) * HWSZ;
                v[q] = cw[0] * __ldg(xc + ci[0]) + cw[1] * __ldg(xc + ci[1])
                     + cw[2] * __ldg(xc + ci[2]) + cw[3] * __ldg(xc + ci[3]);
            }
            unsigned short h[4], l[4];
#pragma unroll
            for (int q = 0; q < 4; q++) {
                __nv_bfloat16 hb = __float2bfloat16(v[q]);
                __nv_bfloat16 lb = __float2bfloat16(v[q] - __bfloat162float(hb));
                h[q] = __bfloat16_as_ushort(hb);
                l[q] = __bfloat16_as_ushort(lb);
            }
            uint2 hp, lp;
            hp.x = ((uint32_t)h[1] << 16) | h[0];
            hp.y = ((uint32_t)h[3] << 16) | h[2];
            lp.x = ((uint32_t)l[1] << 16) | l[0];
            lp.y = ((uint32_t)l[3] << 16) | l[2];
            *(uint2*)(ahp + 8 * j) = hp;
            *(uint2*)(alp + 8 * j) = lp;
        }
    };

    // prologue
    fill(0);
    __syncthreads();

    for (int p = 0; p < 18; p++) {
        // pipeline: fill next phase's buffer (gathers overlap mma below)
        if (p < 17) fill(p + 1);

        // mma over phase p's 32-k chunk from buffer p&1
        const int tap  = p >> 1;
        const int half = p & 1;
        const uint32_t abase = aA + (uint32_t)(half * A_BUF);
#pragma unroll
        for (int ks = 0; ks < 2; ks++) {
            const int kglob = tap * 64 + half * 32 + ks * 16;
            uint32_t ah[4], al[4];
            ldsm4(ah, abase + ks * 32);
            ldsm4(al, abase + A_HALF + ks * 32);
            uint32_t bh[16], bl[16];
            const uint32_t bcol = kglob * 2 + b_k8;
#pragma unroll
            for (int obp = 0; obp < 4; obp++) {
                uint32_t roff = (uint32_t)(obp * 16) * (WPITCH * 2) + b_row_off + bcol;
                ldsm4(&bh[obp * 4], sb + SM_WHI + roff);
                ldsm4(&bl[obp * 4], sb + SM_WLO + roff);
            }
#pragma unroll
            for (int ob = 0; ob < 8; ob++) mma_bf16(acc[ob], ah, &bh[ob * 2]);
#pragma unroll
            for (int ob = 0; ob < 8; ob++) mma_bf16(acc[ob], ah, &bl[ob * 2]);
#pragma unroll
            for (int ob = 0; ob < 8; ob++) mma_bf16(acc[ob], al, &bh[ob * 2]);
        }
        __syncthreads();
    }

    // ---- epilogue: bias + relu ----
    {
        const int prow = px0 + (lane >> 2);
        const int row1 = y0 + (prow >> 7);
        const int x1   = prow & 127;
        const int prow2 = prow + 8;
        const int row2 = y0 + (prow2 >> 7);
        const int x2   = prow2 & 127;
#pragma unroll
        for (int ob = 0; ob < 8; ob++) {
            int o = ob * 8 + (lane & 3) * 2;
            float b0v = __ldg(b_def + o);
            float b1v = __ldg(b_def + o + 1);
            float* p1 = out + (((size_t)(b * OO + o) * HH + row1) * WW + x1);
            float* p2 = out + (((size_t)(b * OO + o) * HH + row2) * WW + x2);
            p1[0]    = fmaxf(acc[ob][0] + b0v, 0.f);
            p1[HWSZ] = fmaxf(acc[ob][1] + b1v, 0.f);
            p2[0]    = fmaxf(acc[ob][2] + b0v, 0.f);
            p2[HWSZ] = fmaxf(acc[ob][3] + b1v, 0.f);
        }
    }
}

// ---------------------------------------------------------------------------
extern "C" void kernel_launch(void* const* d_in, const int* in_sizes, int n_in,
                              void* d_out, int out_size)
{
    const float* x     = (const float*)d_in[0];
    const float* feat  = (const float*)d_in[1];
    const float* w_off = (const float*)d_in[2];
    const float* b_off = (const float*)d_in[3];
    const float* w_def = (const float*)d_in[4];
    const float* b_def = (const float*)d_in[5];
    float* out = (float*)d_out;

    cudaFuncSetAttribute(offset_conv_kernel,
                         cudaFuncAttributeMaxDynamicSharedMemorySize, K1_SMEM_BYTES);
    cudaFuncSetAttribute(deform_mma_kernel,
                         cudaFuncAttributeMaxDynamicSharedMemorySize, K2_SMEM);

    dim3 gridp(OO, 5);
    prep_w_kernel<<<gridp, 128>>>(w_def);
    dim3 grid1(HH / 2, BB);
    offset_conv_kernel<<<grid1, 512, K1_SMEM_BYTES>>>(feat, w_off, b_off);
    dim3 grid2(HH / 2, BB);
    deform_mma_kernel<<<grid2, 512, K2_SMEM>>>(x, b_def, out);
}